// round 4
// baseline (speedup 1.0000x reference)
#include <cuda_runtime.h>
#include <cstdint>

// ---------------------------------------------------------------------------
// Problem constants
// ---------------------------------------------------------------------------
#define N_ROWS 16384      // 64 * 256
#define N_FEAT 2048
#define N_BINS 32
#define NSTRIPE 64
#define RPS (N_ROWS / NSTRIPE)     // 256 rows per stripe
#define TBL 65536
#define NTILE 128                  // 128-row tiles
// project smem: RP' half (512 kk * 32 * 4B) + offset (32 f) + pad
#define PROJ_SMEM (512*32*4 + 128)   // 65664

// ---------------------------------------------------------------------------
// Scratch (static device globals; no runtime allocation)
// ---------------------------------------------------------------------------
__device__ float              g_psum[NSTRIPE * N_FEAT];
__device__ float              g_psq [NSTRIPE * N_FEAT];
__device__ float              g_isig[N_FEAT];
__device__ float              g_m2  [N_FEAT];              // mean * isig
__device__ float              g_off [N_BINS];              // m2 . RP
__device__ unsigned int       g_rppack[1024 * 32];         // bf16x2 isig*RP, swizzled
__device__ float              g_part[2 * N_ROWS * N_BINS]; // split-K partials
__device__ unsigned int       g_tilecnt[NTILE];            // arrival counters
__device__ unsigned int       g_hash[N_ROWS];
__device__ unsigned int       g_slot[N_ROWS];
__device__ unsigned long long g_tkey[TBL];
__device__ unsigned int       g_tcnt[TBL];

// ---------------------------------------------------------------------------
// Helpers
// ---------------------------------------------------------------------------
__device__ __forceinline__ unsigned packbf(float lo, float hi) {
    unsigned d;
    asm("cvt.rn.bf16x2.f32 %0, %1, %2;" : "=r"(d) : "f"(hi), "f"(lo));
    return d;
}

__device__ __forceinline__ void mma16816(float* c,
                                         unsigned a0, unsigned a1, unsigned a2, unsigned a3,
                                         unsigned b0, unsigned b1) {
    asm volatile(
        "mma.sync.aligned.m16n8k16.row.col.f32.bf16.bf16.f32 "
        "{%0,%1,%2,%3}, {%4,%5,%6,%7}, {%8,%9}, {%0,%1,%2,%3};"
        : "+f"(c[0]), "+f"(c[1]), "+f"(c[2]), "+f"(c[3])
        : "r"(a0), "r"(a1), "r"(a2), "r"(a3), "r"(b0), "r"(b1));
}

__device__ __forceinline__ void table_insert(int i, unsigned h) {
    unsigned long long key = ((unsigned long long)h << 6) | (unsigned long long)(i & 63);
    unsigned long long m = key * 0x9E3779B97F4A7C15ULL;
    unsigned s = (unsigned)(m >> 48);   // 16-bit slot
    for (;;) {
        unsigned long long prev = atomicCAS(&g_tkey[s], ~0ULL, key);
        if (prev == ~0ULL || prev == key) {
            atomicAdd(&g_tcnt[s], 1u);
            g_slot[i] = s;
            return;
        }
        s = (s + 1) & (TBL - 1);
    }
}

// ---------------------------------------------------------------------------
// Kernel 1 (fused): column partial sums + table/counter init.
// ---------------------------------------------------------------------------
__global__ void k_pre(const float* __restrict__ x) {
    int b = blockIdx.x;
    if (b < 512) {
        int colblk = b & 7, stripe = b >> 3;
        int col = colblk * 256 + threadIdx.x;
        const float* p = x + (size_t)(stripe * RPS) * N_FEAT + col;
        float s = 0.f, q = 0.f;
#pragma unroll 16
        for (int r = 0; r < RPS; r++) {
            float v = p[(size_t)r * N_FEAT];
            s += v;
            q = fmaf(v, v, q);
        }
        g_psum[stripe * N_FEAT + col] = s;
        g_psq [stripe * N_FEAT + col] = q;
    } else {
        int i = (b - 512) * 256 + threadIdx.x;
        g_tkey[i] = ~0ULL;
        g_tcnt[i] = 0u;
        if (b == 512 && threadIdx.x < NTILE) g_tilecnt[threadIdx.x] = 0u;
    }
}

// ---------------------------------------------------------------------------
// Kernel 2: finalize RunningMeanStd -> isig, mean*isig
// ---------------------------------------------------------------------------
__global__ void k_stats() {
    __shared__ float ss[8][32], sq[8][32];
    int c = threadIdx.x & 31, g = threadIdx.x >> 5;
    int col = blockIdx.x * 32 + c;
    float s = 0.f, q = 0.f;
#pragma unroll
    for (int st = g; st < NSTRIPE; st += 8) {
        s += g_psum[st * N_FEAT + col];
        q += g_psq [st * N_FEAT + col];
    }
    ss[g][c] = s; sq[g][c] = q;
    __syncthreads();
    if (g == 0) {
#pragma unroll
        for (int j = 1; j < 8; j++) { s += ss[j][c]; q += sq[j][c]; }
        const float n = 16384.0f;
        float bm = s / n;
        float bv = (q - bm * bm * n) / (n - 1.0f);       // unbiased variance
        const double nd = 16384.0, totd = 1e-4 + nd;
        float mean = bm * (float)(nd / totd);
        float m2v  = (1e-4f + bv * 16384.0f) + (bm * bm) * (float)(1e-4 * nd / totd);
        float var  = m2v / (float)totd;
        float isg  = 1.0f / sqrtf(var + 1e-8f);
        g_isig[col] = isg;
        g_m2[col]   = mean * isg;
    }
}

// ---------------------------------------------------------------------------
// Kernel 3: RP' = isig*RP packed bf16x2 swizzled (blocks 0..127);
//           offset[b] = sum_k m2[k]*RP[k,b] (block 128).
// ---------------------------------------------------------------------------
__global__ void k_scale(const float* __restrict__ rp) {
    if (blockIdx.x < 128) {
        int idx = blockIdx.x * 256 + threadIdx.x;  // 0..32767
        int kk  = idx >> 5;                        // k-pair index 0..1023
        int col = idx & 31;
        float lo = rp[(2 * kk)     * N_BINS + col] * g_isig[2 * kk];
        float hi = rp[(2 * kk + 1) * N_BINS + col] * g_isig[2 * kk + 1];
        int scol = col ^ ((kk & 3) << 3);
        g_rppack[kk * 32 + scol] = packbf(lo, hi);
    } else {
        __shared__ float red[8][32];
        int b = threadIdx.x & 31, part = threadIdx.x >> 5;   // 8 parts x 256 k
        float s = 0.f;
        for (int k = part * 256; k < part * 256 + 256; k++)
            s = fmaf(g_m2[k], rp[k * N_BINS + b], s);
        red[part][b] = s;
        __syncthreads();
        if (part == 0) {
#pragma unroll
            for (int j = 1; j < 8; j++) s += red[j][b];
            g_off[b] = s;
        }
    }
}

// ---------------------------------------------------------------------------
// Kernel 4: split-K raw-x bf16 mma projection -> fp32 partials -> (last
// arriving half per tile) combine + offset + sign hash + table insert.
//   256 blocks: tile = bid>>1, kh = bid&1. 64KB smem -> 3 blocks/SM.
// ---------------------------------------------------------------------------
__global__ void __launch_bounds__(256, 3) k_project(const float* __restrict__ x) {
    extern __shared__ unsigned int smem[];          // [0,16384): RP' half (64KB)
    float* soff = (float*)(smem + 16384);           // [32]
    __shared__ int s_last;

    int tile = blockIdx.x >> 1;
    int kh   = blockIdx.x & 1;
    int kbase = kh * 1024;

    const unsigned* rpsrc = g_rppack + kh * 512 * 32;   // swizzle parity kept
    for (int idx = threadIdx.x; idx < 16384; idx += 256) smem[idx] = rpsrc[idx];
    if (threadIdx.x < 32) soff[threadIdx.x] = g_off[threadIdx.x];
    __syncthreads();

    int warp = threadIdx.x >> 5, lane = threadIdx.x & 31;
    int q = lane & 3, r = lane >> 2;
    int row0 = tile * 128 + warp * 16;

    const float* xa = x + (size_t)(row0 + r) * N_FEAT + kbase + 2 * q;
    const float* xb = xa + 8 * (size_t)N_FEAT;

    float acc[4][4];
#pragma unroll
    for (int t = 0; t < 4; t++)
#pragma unroll
        for (int c = 0; c < 4; c++) acc[t][c] = 0.f;

    unsigned scol[4];
#pragma unroll
    for (int t = 0; t < 4; t++) scol[t] = (unsigned)((t * 8 + r) ^ (q << 3));

#pragma unroll 4
    for (int k = 0; k < 1024; k += 16) {
        float2 va = *(const float2*)(xa + k);
        float2 vb = *(const float2*)(xa + k + 8);
        float2 vc = *(const float2*)(xb + k);
        float2 vd = *(const float2*)(xb + k + 8);

        unsigned a0 = packbf(va.x, va.y);
        unsigned a2 = packbf(vb.x, vb.y);
        unsigned a1 = packbf(vc.x, vc.y);
        unsigned a3 = packbf(vd.x, vd.y);

        int kk = (k >> 1) + q;
#pragma unroll
        for (int t = 0; t < 4; t++) {
            unsigned b0 = smem[kk * 32 + scol[t]];
            unsigned b1 = smem[(kk + 4) * 32 + scol[t]];
            mma16816(acc[t], a0, a1, a2, a3, b0, b1);
        }
    }

    // publish my half's partials
    float* dst = g_part + (size_t)kh * N_ROWS * N_BINS;
    int rowA = row0 + r, rowB = rowA + 8;
#pragma unroll
    for (int t = 0; t < 4; t++) {
        int cb = t * 8 + 2 * q;
        *(float2*)(dst + (size_t)rowA * N_BINS + cb) = make_float2(acc[t][0], acc[t][1]);
        *(float2*)(dst + (size_t)rowB * N_BINS + cb) = make_float2(acc[t][2], acc[t][3]);
    }
    __threadfence();
    if (threadIdx.x == 0) s_last = (int)atomicAdd(&g_tilecnt[tile], 1u);
    __syncthreads();
    if (s_last != 1) return;       // first-arriving half is done
    __threadfence();               // make peer's partials visible

    // last-arriving half: add peer partials (L2), subtract offset, sign
    const float* src = g_part + (size_t)(1 - kh) * N_ROWS * N_BINS;
    unsigned mlo = 0u, mhi = 0u;
#pragma unroll
    for (int t = 0; t < 4; t++) {
        int cb = t * 8 + 2 * q;
        float2 pa = *(const float2*)(src + (size_t)rowA * N_BINS + cb);
        float2 pb = *(const float2*)(src + (size_t)rowB * N_BINS + cb);
        float o0 = soff[cb], o1 = soff[cb + 1];
        mlo |= ((acc[t][0] + pa.x - o0) > 0.f ? 1u : 0u) << cb;
        mlo |= ((acc[t][1] + pa.y - o1) > 0.f ? 1u : 0u) << (cb + 1);
        mhi |= ((acc[t][2] + pb.x - o0) > 0.f ? 1u : 0u) << cb;
        mhi |= ((acc[t][3] + pb.y - o1) > 0.f ? 1u : 0u) << (cb + 1);
    }
    mlo |= __shfl_xor_sync(0xffffffffu, mlo, 1);
    mlo |= __shfl_xor_sync(0xffffffffu, mlo, 2);
    mhi |= __shfl_xor_sync(0xffffffffu, mhi, 1);
    mhi |= __shfl_xor_sync(0xffffffffu, mhi, 2);

    if (q == 0) {
        g_hash[rowA] = mlo;
        g_hash[rowB] = mhi;
        table_insert(rowA, mlo);
        table_insert(rowB, mhi);
    }
}

// ---------------------------------------------------------------------------
// Kernel 5: rewards. Unique keys -> 1.0; rare duplicates get exact rank.
// ---------------------------------------------------------------------------
__global__ void k_final(float* __restrict__ out) {
    int i = blockIdx.x * 128 + threadIdx.x;
    unsigned s = g_slot[i];
    float v = 1.0f;
    if (g_tcnt[s] != 1u) {
        unsigned long long my = ((unsigned long long)g_hash[i] << 6) | (unsigned long long)(i & 63);
        int c = 1;
        for (int j = 0; j < i; j++) {
            unsigned long long kj = ((unsigned long long)g_hash[j] << 6) | (unsigned long long)(j & 63);
            c += (kj == my) ? 1 : 0;
        }
        v = 1.0f / sqrtf((float)c);
    }
    out[i] = v;
}

// ---------------------------------------------------------------------------
// Launch
// ---------------------------------------------------------------------------
extern "C" void kernel_launch(void* const* d_in, const int* in_sizes, int n_in,
                              void* d_out, int out_size) {
    const float* x  = (const float*)d_in[0];
    const float* rp = (const float*)d_in[1];
    if (in_sizes[0] == N_FEAT * N_BINS) {   // defensive: swap if order differs
        const float* t = x; x = rp; rp = t;
    }
    float* out = (float*)d_out;

    cudaFuncSetAttribute(k_project, cudaFuncAttributeMaxDynamicSharedMemorySize, PROJ_SMEM);

    k_pre    <<<768, 256>>>(x);
    k_stats  <<<64, 256>>>();
    k_scale  <<<129, 256>>>(rp);
    k_project<<<256, 256, PROJ_SMEM>>>(x);
    k_final  <<<128, 128>>>(out);
}